// round 1
// baseline (speedup 1.0000x reference)
#include <cuda_runtime.h>
#include <cstdint>

// ---------------------------------------------------------------------------
// MockLoHAAdapter: y = x @ (W + (w1a@w1b) * (w2a@w2b) * scalar)^T + bias
//   x: [4, 2048, 4096] f32   W: [4096, 4096] f32   bias: [4096] f32
//   w1a/w2a: [4096, 16]      w1b/w2b: [16, 4096]   scalar: [] f32
// Plan: (1) materialize combined weight Wc into device-global scratch,
//       (2) tf32 mma.sync GEMM  y[8192,4096] = x @ Wc^T + bias.
// ---------------------------------------------------------------------------

#define IN_DIM   4096
#define OUT_DIM  4096
#define RANK     16
#define M_TOTAL  8192   // 4 * 2048

// 64 MB scratch for combined weight (allocation-free rule: __device__ global).
__device__ float g_Wc[(size_t)OUT_DIM * IN_DIM];

// ---------------------------------------------------------------------------
// Kernel 1: Wc[o][i] = W[o][i] + (w1a[o]·w1b[:,i]) * (w2a[o]·w2b[:,i]) * scalar
// grid (4, 4096), 256 threads; each thread does one float4 (4 i's).
// ---------------------------------------------------------------------------
__global__ __launch_bounds__(256) void prep_weight_kernel(
    const float* __restrict__ W,
    const float* __restrict__ w1a, const float* __restrict__ w1b,
    const float* __restrict__ w2a, const float* __restrict__ w2b,
    const float* __restrict__ scalar)
{
    const int o  = blockIdx.y;
    const int i4 = blockIdx.x * blockDim.x + threadIdx.x;  // float4 index, 0..1023
    const float s = scalar[0];

    const float4* b1p = reinterpret_cast<const float4*>(w1b);
    const float4* b2p = reinterpret_cast<const float4*>(w2b);

    float4 s1 = make_float4(0.f, 0.f, 0.f, 0.f);
    float4 s2 = make_float4(0.f, 0.f, 0.f, 0.f);

#pragma unroll
    for (int r = 0; r < RANK; r++) {
        const float a1 = __ldg(&w1a[o * RANK + r]);
        const float a2 = __ldg(&w2a[o * RANK + r]);
        const float4 b1 = __ldg(&b1p[r * (IN_DIM / 4) + i4]);
        const float4 b2 = __ldg(&b2p[r * (IN_DIM / 4) + i4]);
        s1.x = fmaf(a1, b1.x, s1.x); s1.y = fmaf(a1, b1.y, s1.y);
        s1.z = fmaf(a1, b1.z, s1.z); s1.w = fmaf(a1, b1.w, s1.w);
        s2.x = fmaf(a2, b2.x, s2.x); s2.y = fmaf(a2, b2.y, s2.y);
        s2.z = fmaf(a2, b2.z, s2.z); s2.w = fmaf(a2, b2.w, s2.w);
    }

    const float4 w = __ldg(reinterpret_cast<const float4*>(W) + (size_t)o * (IN_DIM / 4) + i4);
    float4 out;
    out.x = w.x + s1.x * s2.x * s;
    out.y = w.y + s1.y * s2.y * s;
    out.z = w.z + s1.z * s2.z * s;
    out.w = w.w + s1.w * s2.w * s;
    reinterpret_cast<float4*>(g_Wc)[(size_t)o * (IN_DIM / 4) + i4] = out;
}

// ---------------------------------------------------------------------------
// Kernel 2: tf32 tensor-core GEMM.  y[m][n] = sum_k x[m][k] * Wc[n][k] + bias[n]
// Tiles: BM=128, BN=128, BK=32. 256 threads = 8 warps (4 M x 2 N), warp 32x64.
// mma.sync.aligned.m16n8k8.row.col.f32.tf32.tf32.f32
// ---------------------------------------------------------------------------

__device__ __forceinline__ uint32_t f2tf32(float f) {
    uint32_t r;
    asm("cvt.rna.tf32.f32 %0, %1;" : "=r"(r) : "f"(f));   // unbiased rounding
    return r;
}

__device__ __forceinline__ void mma_tf32(float c[4], const uint32_t a[4],
                                         uint32_t b0, uint32_t b1) {
    asm volatile(
        "mma.sync.aligned.m16n8k8.row.col.f32.tf32.tf32.f32 "
        "{%0,%1,%2,%3}, {%4,%5,%6,%7}, {%8,%9}, {%0,%1,%2,%3};"
        : "+f"(c[0]), "+f"(c[1]), "+f"(c[2]), "+f"(c[3])
        : "r"(a[0]), "r"(a[1]), "r"(a[2]), "r"(a[3]), "r"(b0), "r"(b1));
}

#define SMEM_LD 36   // 32 + 4 pad (float4-aligned, conflict-free frag loads)

__global__ __launch_bounds__(256) void gemm_tf32_kernel(
    const float* __restrict__ x,
    const float* __restrict__ bias,
    float* __restrict__ y)
{
    __shared__ uint32_t As[128][SMEM_LD];   // As[m][k]
    __shared__ uint32_t Bs[128][SMEM_LD];   // Bs[n][k]

    const int tid  = threadIdx.x;
    const int lane = tid & 31;
    const int warp = tid >> 5;
    const int wm   = (warp >> 1) * 32;   // warp M offset within block tile
    const int wn   = (warp & 1) * 64;    // warp N offset
    const int lr   = lane >> 2;          // 0..7
    const int lc   = lane & 3;           // 0..3

    const int bm = blockIdx.y;           // M tile (64 tiles)
    const int bn = blockIdx.x;           // N tile (32 tiles)

    float acc[2][8][4];
#pragma unroll
    for (int mi = 0; mi < 2; mi++)
#pragma unroll
        for (int ni = 0; ni < 8; ni++)
#pragma unroll
            for (int q = 0; q < 4; q++) acc[mi][ni][q] = 0.f;

    // Global-load mapping: 128 rows x 8 float4 per row = 1024 float4, 256 thr x 4.
    const int grow  = tid >> 3;          // 0..31 (+p*32)
    const int gcol4 = (tid & 7) * 4;     // 0,4,...,28

    const float* Aptr = x    + (size_t)(bm * 128) * IN_DIM;
    const float* Bptr = g_Wc + (size_t)(bn * 128) * IN_DIM;

    for (int kt = 0; kt < IN_DIM; kt += 32) {
#pragma unroll
        for (int p = 0; p < 4; p++) {
            const int row = grow + p * 32;
            const float4 va = *reinterpret_cast<const float4*>(
                Aptr + (size_t)row * IN_DIM + kt + gcol4);
            const float4 vb = *reinterpret_cast<const float4*>(
                Bptr + (size_t)row * IN_DIM + kt + gcol4);
            As[row][gcol4 + 0] = f2tf32(va.x);
            As[row][gcol4 + 1] = f2tf32(va.y);
            As[row][gcol4 + 2] = f2tf32(va.z);
            As[row][gcol4 + 3] = f2tf32(va.w);
            Bs[row][gcol4 + 0] = f2tf32(vb.x);
            Bs[row][gcol4 + 1] = f2tf32(vb.y);
            Bs[row][gcol4 + 2] = f2tf32(vb.z);
            Bs[row][gcol4 + 3] = f2tf32(vb.w);
        }
        __syncthreads();

#pragma unroll
        for (int ks = 0; ks < 4; ks++) {
            const int k0 = ks * 8;
            uint32_t a[2][4];
#pragma unroll
            for (int mi = 0; mi < 2; mi++) {
                const int r = wm + mi * 16 + lr;
                a[mi][0] = As[r][k0 + lc];
                a[mi][1] = As[r + 8][k0 + lc];
                a[mi][2] = As[r][k0 + lc + 4];
                a[mi][3] = As[r + 8][k0 + lc + 4];
            }
#pragma unroll
            for (int ni = 0; ni < 8; ni++) {
                const int r = wn + ni * 8 + lr;
                const uint32_t b0 = Bs[r][k0 + lc];
                const uint32_t b1 = Bs[r][k0 + lc + 4];
                mma_tf32(acc[0][ni], a[0], b0, b1);
                mma_tf32(acc[1][ni], a[1], b0, b1);
            }
        }
        __syncthreads();
    }

    // Epilogue: y = acc + bias
    float* yb = y + (size_t)(bm * 128 + wm) * OUT_DIM + bn * 128 + wn;
    const float* biasb = bias + bn * 128 + wn;
#pragma unroll
    for (int mi = 0; mi < 2; mi++) {
#pragma unroll
        for (int ni = 0; ni < 8; ni++) {
            const int col = ni * 8 + lc * 2;
            const float2 bb = *reinterpret_cast<const float2*>(biasb + col);
            float2 v0 = make_float2(acc[mi][ni][0] + bb.x, acc[mi][ni][1] + bb.y);
            float2 v1 = make_float2(acc[mi][ni][2] + bb.x, acc[mi][ni][3] + bb.y);
            *reinterpret_cast<float2*>(yb + (size_t)(mi * 16 + lr) * OUT_DIM + col)     = v0;
            *reinterpret_cast<float2*>(yb + (size_t)(mi * 16 + lr + 8) * OUT_DIM + col) = v1;
        }
    }
}

// ---------------------------------------------------------------------------
extern "C" void kernel_launch(void* const* d_in, const int* in_sizes, int n_in,
                              void* d_out, int out_size)
{
    const float* x      = (const float*)d_in[0];
    const float* W      = (const float*)d_in[1];
    const float* bias   = (const float*)d_in[2];
    const float* w1a    = (const float*)d_in[3];
    const float* w1b    = (const float*)d_in[4];
    const float* w2a    = (const float*)d_in[5];
    const float* w2b    = (const float*)d_in[6];
    const float* scalar = (const float*)d_in[7];
    float* y = (float*)d_out;

    (void)in_sizes; (void)n_in; (void)out_size;

    // 1) Combined weight Wc = W + (w1a@w1b)*(w2a@w2b)*scalar
    prep_weight_kernel<<<dim3(4, OUT_DIM), 256>>>(W, w1a, w1b, w2a, w2b, scalar);

    // 2) y = x @ Wc^T + bias   (M=8192, N=4096, K=4096)
    gemm_tf32_kernel<<<dim3(OUT_DIM / 128, M_TOTAL / 128), 256>>>(x, bias, y);
}

// round 2
// speedup vs baseline: 1.3659x; 1.3659x over previous
#include <cuda_runtime.h>
#include <cstdint>

// ---------------------------------------------------------------------------
// MockLoHAAdapter: y = x @ (W + (w1a@w1b) * (w2a@w2b) * scalar)^T + bias
// Round 2: pre-convert x and Wc to tf32 bits; 3-stage cp.async-pipelined
// tf32 mma.sync GEMM with zero conversions in the hot loop.
// ---------------------------------------------------------------------------

#define IN_DIM   4096
#define OUT_DIM  4096
#define RANK     16
#define M_TOTAL  8192   // 4 * 2048

#define BK        32
#define NSTAGE    3
#define ROW_LD    36                     // 32 + 4 pad words; 144B row (16B-aligned)
#define STAGE_WORDS (2 * 128 * ROW_LD)   // A tile + B tile per stage
#define SMEM_BYTES  (NSTAGE * STAGE_WORDS * 4)   // 110592

// Device-global scratch (allocation-free rule): tf32-bit operands.
__device__ uint32_t g_Wc[(size_t)OUT_DIM * IN_DIM];   // combined weight, tf32 bits
__device__ uint32_t g_Xc[(size_t)M_TOTAL * IN_DIM];   // x, tf32 bits

__device__ __forceinline__ uint32_t f2tf32(float f) {
    uint32_t r;
    asm("cvt.rna.tf32.f32 %0, %1;" : "=r"(r) : "f"(f));
    return r;
}

// ---------------------------------------------------------------------------
// Kernel 1: Wc = (W + (w1a@w1b)*(w2a@w2b)*scalar) converted to tf32 bits.
// ---------------------------------------------------------------------------
__global__ __launch_bounds__(256) void prep_weight_kernel(
    const float* __restrict__ W,
    const float* __restrict__ w1a, const float* __restrict__ w1b,
    const float* __restrict__ w2a, const float* __restrict__ w2b,
    const float* __restrict__ scalar)
{
    const int o  = blockIdx.y;
    const int i4 = blockIdx.x * blockDim.x + threadIdx.x;  // float4 index 0..1023
    const float s = scalar[0];

    const float4* b1p = reinterpret_cast<const float4*>(w1b);
    const float4* b2p = reinterpret_cast<const float4*>(w2b);

    float4 s1 = make_float4(0.f, 0.f, 0.f, 0.f);
    float4 s2 = make_float4(0.f, 0.f, 0.f, 0.f);

#pragma unroll
    for (int r = 0; r < RANK; r++) {
        const float a1 = __ldg(&w1a[o * RANK + r]);
        const float a2 = __ldg(&w2a[o * RANK + r]);
        const float4 b1 = __ldg(&b1p[r * (IN_DIM / 4) + i4]);
        const float4 b2 = __ldg(&b2p[r * (IN_DIM / 4) + i4]);
        s1.x = fmaf(a1, b1.x, s1.x); s1.y = fmaf(a1, b1.y, s1.y);
        s1.z = fmaf(a1, b1.z, s1.z); s1.w = fmaf(a1, b1.w, s1.w);
        s2.x = fmaf(a2, b2.x, s2.x); s2.y = fmaf(a2, b2.y, s2.y);
        s2.z = fmaf(a2, b2.z, s2.z); s2.w = fmaf(a2, b2.w, s2.w);
    }

    const float4 w = __ldg(reinterpret_cast<const float4*>(W) + (size_t)o * (IN_DIM / 4) + i4);
    uint4 out;
    out.x = f2tf32(w.x + s1.x * s2.x * s);
    out.y = f2tf32(w.y + s1.y * s2.y * s);
    out.z = f2tf32(w.z + s1.z * s2.z * s);
    out.w = f2tf32(w.w + s1.w * s2.w * s);
    reinterpret_cast<uint4*>(g_Wc)[(size_t)o * (IN_DIM / 4) + i4] = out;
}

// ---------------------------------------------------------------------------
// Kernel 2: convert x to tf32 bits (pure bandwidth, ~32 us).
// ---------------------------------------------------------------------------
__global__ __launch_bounds__(256) void convert_x_kernel(const float* __restrict__ x)
{
    const size_t i = (size_t)blockIdx.x * blockDim.x + threadIdx.x;  // float4 idx
    const float4 v = __ldg(reinterpret_cast<const float4*>(x) + i);
    uint4 o;
    o.x = f2tf32(v.x); o.y = f2tf32(v.y); o.z = f2tf32(v.z); o.w = f2tf32(v.w);
    reinterpret_cast<uint4*>(g_Xc)[i] = o;
}

// ---------------------------------------------------------------------------
// Kernel 3: pipelined tf32 GEMM.  y[m][n] = x[m][:]·Wc[n][:] + bias[n]
// BM=BN=128, BK=32, 256 thr (8 warps: 4M x 2N, warp tile 32x64), 3-stage cp.async.
// ---------------------------------------------------------------------------

__device__ __forceinline__ void mma_tf32(float c[4], const uint32_t a[4],
                                         uint32_t b0, uint32_t b1) {
    asm volatile(
        "mma.sync.aligned.m16n8k8.row.col.f32.tf32.tf32.f32 "
        "{%0,%1,%2,%3}, {%4,%5,%6,%7}, {%8,%9}, {%0,%1,%2,%3};"
        : "+f"(c[0]), "+f"(c[1]), "+f"(c[2]), "+f"(c[3])
        : "r"(a[0]), "r"(a[1]), "r"(a[2]), "r"(a[3]), "r"(b0), "r"(b1));
}

__device__ __forceinline__ void cp_async16(uint32_t smem_addr, const void* gptr) {
    asm volatile("cp.async.cg.shared.global [%0], [%1], 16;\n"
                 :: "r"(smem_addr), "l"(gptr));
}

__global__ __launch_bounds__(256) void gemm_tf32_pipe(
    const float* __restrict__ bias, float* __restrict__ y)
{
    extern __shared__ uint32_t sm[];

    const int tid  = threadIdx.x;
    const int lane = tid & 31;
    const int warp = tid >> 5;
    const int wm   = (warp >> 1) * 32;
    const int wn   = (warp & 1) * 64;
    const int lr   = lane >> 2;   // 0..7
    const int lc   = lane & 3;    // 0..3

    const int bm = blockIdx.y;
    const int bn = blockIdx.x;

    const uint32_t* Aptr = g_Xc + (size_t)(bm * 128) * IN_DIM;
    const uint32_t* Bptr = g_Wc + (size_t)(bn * 128) * IN_DIM;

    // cp.async fill mapping: chunk c in [0,1024): row=c>>3, word-col=(c&7)*4.
    const int c_row = tid >> 3;          // +p*32
    const int c_colw = (tid & 7) * 4;

    const uint32_t smem_base = (uint32_t)__cvta_generic_to_shared(sm);

    auto issue_stage = [&](int kt, int s) {
        const uint32_t a_base = smem_base + (uint32_t)(s * STAGE_WORDS) * 4;
        const uint32_t b_base = a_base + 128 * ROW_LD * 4;
        const int kofs = kt * BK + c_colw;
#pragma unroll
        for (int p = 0; p < 4; p++) {
            const int row = c_row + p * 32;
            const uint32_t so = (uint32_t)(row * ROW_LD + c_colw) * 4;
            cp_async16(a_base + so, Aptr + (size_t)row * IN_DIM + kofs);
            cp_async16(b_base + so, Bptr + (size_t)row * IN_DIM + kofs);
        }
    };

    float acc[2][8][4];
#pragma unroll
    for (int mi = 0; mi < 2; mi++)
#pragma unroll
        for (int ni = 0; ni < 8; ni++)
#pragma unroll
            for (int q = 0; q < 4; q++) acc[mi][ni][q] = 0.f;

    const int NT = IN_DIM / BK;   // 128 k-tiles

    issue_stage(0, 0);
    asm volatile("cp.async.commit_group;\n" ::);
    issue_stage(1, 1);
    asm volatile("cp.async.commit_group;\n" ::);

    for (int kt = 0; kt < NT; kt++) {
        asm volatile("cp.async.wait_group 1;\n" ::);
        __syncthreads();

        if (kt + 2 < NT) issue_stage(kt + 2, (kt + 2) % NSTAGE);
        asm volatile("cp.async.commit_group;\n" ::);   // empty groups in tail keep count

        const uint32_t* As = sm + (kt % NSTAGE) * STAGE_WORDS;
        const uint32_t* Bs = As + 128 * ROW_LD;

#pragma unroll
        for (int ks = 0; ks < 4; ks++) {
            const int k0 = ks * 8;
            uint32_t a[2][4];
#pragma unroll
            for (int mi = 0; mi < 2; mi++) {
                const int r = wm + mi * 16 + lr;
                a[mi][0] = As[r * ROW_LD + k0 + lc];
                a[mi][1] = As[(r + 8) * ROW_LD + k0 + lc];
                a[mi][2] = As[r * ROW_LD + k0 + lc + 4];
                a[mi][3] = As[(r + 8) * ROW_LD + k0 + lc + 4];
            }
#pragma unroll
            for (int ni = 0; ni < 8; ni++) {
                const int r = wn + ni * 8 + lr;
                const uint32_t b0 = Bs[r * ROW_LD + k0 + lc];
                const uint32_t b1 = Bs[r * ROW_LD + k0 + lc + 4];
                mma_tf32(acc[0][ni], a[0], b0, b1);
                mma_tf32(acc[1][ni], a[1], b0, b1);
            }
        }
    }

    // Epilogue: y = acc + bias
    float* yb = y + (size_t)(bm * 128 + wm) * OUT_DIM + bn * 128 + wn;
    const float* biasb = bias + bn * 128 + wn;
#pragma unroll
    for (int mi = 0; mi < 2; mi++) {
#pragma unroll
        for (int ni = 0; ni < 8; ni++) {
            const int col = ni * 8 + lc * 2;
            const float2 bb = *reinterpret_cast<const float2*>(biasb + col);
            float2 v0 = make_float2(acc[mi][ni][0] + bb.x, acc[mi][ni][1] + bb.y);
            float2 v1 = make_float2(acc[mi][ni][2] + bb.x, acc[mi][ni][3] + bb.y);
            *reinterpret_cast<float2*>(yb + (size_t)(mi * 16 + lr) * OUT_DIM + col)     = v0;
            *reinterpret_cast<float2*>(yb + (size_t)(mi * 16 + lr + 8) * OUT_DIM + col) = v1;
        }
    }
}

// ---------------------------------------------------------------------------
extern "C" void kernel_launch(void* const* d_in, const int* in_sizes, int n_in,
                              void* d_out, int out_size)
{
    const float* x      = (const float*)d_in[0];
    const float* W      = (const float*)d_in[1];
    const float* bias   = (const float*)d_in[2];
    const float* w1a    = (const float*)d_in[3];
    const float* w1b    = (const float*)d_in[4];
    const float* w2a    = (const float*)d_in[5];
    const float* w2b    = (const float*)d_in[6];
    const float* scalar = (const float*)d_in[7];
    float* y = (float*)d_out;

    (void)in_sizes; (void)n_in; (void)out_size;

    static bool attr_set = false;
    if (!attr_set) {
        cudaFuncSetAttribute(gemm_tf32_pipe,
                             cudaFuncAttributeMaxDynamicSharedMemorySize, SMEM_BYTES);
        attr_set = true;
    }

    prep_weight_kernel<<<dim3(4, OUT_DIM), 256>>>(W, w1a, w1b, w2a, w2b, scalar);
    convert_x_kernel<<<(M_TOTAL * (size_t)IN_DIM / 4) / 256, 256>>>(x);
    gemm_tf32_pipe<<<dim3(OUT_DIM / 128, M_TOTAL / 128), 256, SMEM_BYTES>>>(bias, y);
}

// round 7
// speedup vs baseline: 2.3588x; 1.7269x over previous
#include <cuda_runtime.h>
#include <cuda_fp16.h>
#include <cstdint>

// ---------------------------------------------------------------------------
// MockLoHAAdapter: y = x @ (W + (w1a@w1b)*(w2a@w2b)*scalar)^T + bias
// Round 5: fp16 mma.sync m16n8k16 (2x MACs/instr vs tf32, same 11-bit
// significand), 5-stage cp.async pipeline, fp16 pre-converted operands.
// (Round 4 with the __half2_as_uint compile error fixed.)
// ---------------------------------------------------------------------------

#define IN_DIM   4096
#define OUT_DIM  4096
#define RANK     16
#define M_TOTAL  8192

#define BK        64                     // halfs per k-tile -> 128 B/row
#define NT        (IN_DIM / BK)          // 64 k-tiles
#define NSTAGE    5
#define ROW_HALFS 72                     // 64 + 8 pad (144 B, 16B-aligned)
#define TILE_HALFS (128 * ROW_HALFS)
#define STAGE_HALFS (2 * TILE_HALFS)     // A + B
#define SMEM_BYTES  (NSTAGE * STAGE_HALFS * 2)   // 184320

// Device-global fp16 operands (allocation-free rule).
__device__ __half g_Wh[(size_t)OUT_DIM * IN_DIM];
__device__ __half g_Xh[(size_t)M_TOTAL * IN_DIM];

// ---------------------------------------------------------------------------
// Kernel 1: Wc = (W + (w1a@w1b)*(w2a@w2b)*scalar) -> fp16.
// Block: o-tile 128 x i-tile 256; smem-staged rank factors.
// ---------------------------------------------------------------------------
__global__ __launch_bounds__(256) void prep_weight_kernel(
    const float* __restrict__ W,
    const float* __restrict__ w1a, const float* __restrict__ w1b,
    const float* __restrict__ w2a, const float* __restrict__ w2b,
    const float* __restrict__ scalar)
{
    __shared__ float b1s[RANK][256];
    __shared__ float b2s[RANK][256];
    __shared__ float a1s[128][RANK];
    __shared__ float a2s[128][RANK];

    const int tid = threadIdx.x;
    const int i0 = blockIdx.x * 256;
    const int o0 = blockIdx.y * 128;
    const float s = scalar[0];

#pragma unroll
    for (int j = 0; j < RANK; j++) {
        b1s[j][tid] = w1b[j * IN_DIM + i0 + tid];
        b2s[j][tid] = w2b[j * IN_DIM + i0 + tid];
    }
#pragma unroll
    for (int j = 0; j < 8; j++) {
        const int idx = j * 256 + tid;          // 2048 = 128*16
        a1s[idx >> 4][idx & 15] = w1a[(o0 + (idx >> 4)) * RANK + (idx & 15)];
        a2s[idx >> 4][idx & 15] = w2a[(o0 + (idx >> 4)) * RANK + (idx & 15)];
    }
    __syncthreads();

    // Each thread owns column i_local = tid; hoist b-vectors to registers.
    float b1v[RANK], b2v[RANK];
#pragma unroll
    for (int r = 0; r < RANK; r++) { b1v[r] = b1s[r][tid]; b2v[r] = b2s[r][tid]; }

    for (int o = 0; o < 128; o++) {
        float s1 = 0.f, s2 = 0.f;
#pragma unroll
        for (int r = 0; r < RANK; r++) {
            s1 = fmaf(a1s[o][r], b1v[r], s1);
            s2 = fmaf(a2s[o][r], b2v[r], s2);
        }
        const float w = __ldg(&W[(size_t)(o0 + o) * IN_DIM + i0 + tid]);
        g_Wh[(size_t)(o0 + o) * IN_DIM + i0 + tid] = __float2half_rn(w + s1 * s2 * s);
    }
}

// ---------------------------------------------------------------------------
// Kernel 2: x -> fp16.
// ---------------------------------------------------------------------------
__global__ __launch_bounds__(256) void convert_x_kernel(const float* __restrict__ x)
{
    const size_t i = (size_t)blockIdx.x * blockDim.x + threadIdx.x;  // float4 idx
    const float4 v = __ldg(reinterpret_cast<const float4*>(x) + i);
    const __half2 h0 = __floats2half2_rn(v.x, v.y);
    const __half2 h1 = __floats2half2_rn(v.z, v.w);
    uint2 o;
    o.x = *reinterpret_cast<const uint32_t*>(&h0);
    o.y = *reinterpret_cast<const uint32_t*>(&h1);
    reinterpret_cast<uint2*>(g_Xh)[i] = o;
}

// ---------------------------------------------------------------------------
// Kernel 3: fp16 GEMM. BM=BN=128, BK=64, 256 thr (8 warps: 4M x 2N, warp 32x64).
// ---------------------------------------------------------------------------
__device__ __forceinline__ void mma_f16(float c[4], const uint32_t a[4],
                                        uint32_t b0, uint32_t b1) {
    asm volatile(
        "mma.sync.aligned.m16n8k16.row.col.f32.f16.f16.f32 "
        "{%0,%1,%2,%3}, {%4,%5,%6,%7}, {%8,%9}, {%0,%1,%2,%3};"
        : "+f"(c[0]), "+f"(c[1]), "+f"(c[2]), "+f"(c[3])
        : "r"(a[0]), "r"(a[1]), "r"(a[2]), "r"(a[3]), "r"(b0), "r"(b1));
}

__device__ __forceinline__ void cp_async16(uint32_t smem_addr, const void* gptr) {
    asm volatile("cp.async.cg.shared.global [%0], [%1], 16;\n"
                 :: "r"(smem_addr), "l"(gptr));
}

__global__ __launch_bounds__(256, 1) void gemm_f16_pipe(
    const float* __restrict__ bias, float* __restrict__ y)
{
    extern __shared__ __align__(16) __half sm[];

    const int tid  = threadIdx.x;
    const int lane = tid & 31;
    const int warp = tid >> 5;
    const int wm   = (warp >> 1) * 32;
    const int wn   = (warp & 1) * 64;
    const int lr   = lane >> 2;   // 0..7
    const int lc   = lane & 3;    // 0..3

    const int bm = blockIdx.y;
    const int bn = blockIdx.x;

    const __half* Aptr = g_Xh + (size_t)(bm * 128) * IN_DIM;
    const __half* Bptr = g_Wh + (size_t)(bn * 128) * IN_DIM;

    const uint32_t smem_base = (uint32_t)__cvta_generic_to_shared(sm);

    // Fill: 1024 16B-chunks per operand; chunk c = p*256 + tid:
    // row = c>>3 (0..127), col16 = c&7.
    auto issue_stage = [&](int kt, int s) {
        const uint32_t st = smem_base + (uint32_t)(s * STAGE_HALFS) * 2;
        const int kofs = kt * BK;
#pragma unroll
        for (int p = 0; p < 4; p++) {
            const int c = p * 256 + tid;
            const int row = c >> 3;
            const int col16 = c & 7;
            const uint32_t so = (uint32_t)(row * ROW_HALFS * 2 + col16 * 16);
            const size_t go = (size_t)row * IN_DIM + kofs + col16 * 8;
            cp_async16(st + so,                  Aptr + go);
            cp_async16(st + TILE_HALFS * 2 + so, Bptr + go);
        }
    };

    float acc[2][8][4];
#pragma unroll
    for (int mi = 0; mi < 2; mi++)
#pragma unroll
        for (int ni = 0; ni < 8; ni++)
#pragma unroll
            for (int q = 0; q < 4; q++) acc[mi][ni][q] = 0.f;

#pragma unroll
    for (int i = 0; i < NSTAGE - 1; i++) {
        issue_stage(i, i);
        asm volatile("cp.async.commit_group;\n" ::);
    }

    for (int kt = 0; kt < NT; kt++) {
        asm volatile("cp.async.wait_group %0;\n" :: "n"(NSTAGE - 2));
        __syncthreads();

        if (kt + NSTAGE - 1 < NT) issue_stage(kt + NSTAGE - 1, (kt + NSTAGE - 1) % NSTAGE);
        asm volatile("cp.async.commit_group;\n" ::);

        const __half* As = sm + (kt % NSTAGE) * STAGE_HALFS;
        const __half* Bs = As + TILE_HALFS;

#pragma unroll
        for (int ks = 0; ks < 4; ks++) {
            const int k0 = ks * 16;
            uint32_t a[2][4];
#pragma unroll
            for (int mi = 0; mi < 2; mi++) {
                const int r = wm + mi * 16 + lr;
                a[mi][0] = *reinterpret_cast<const uint32_t*>(&As[r * ROW_HALFS + k0 + lc * 2]);
                a[mi][1] = *reinterpret_cast<const uint32_t*>(&As[(r + 8) * ROW_HALFS + k0 + lc * 2]);
                a[mi][2] = *reinterpret_cast<const uint32_t*>(&As[r * ROW_HALFS + k0 + lc * 2 + 8]);
                a[mi][3] = *reinterpret_cast<const uint32_t*>(&As[(r + 8) * ROW_HALFS + k0 + lc * 2 + 8]);
            }
#pragma unroll
            for (int ni = 0; ni < 8; ni++) {
                const int r = wn + ni * 8 + lr;
                const uint32_t b0 = *reinterpret_cast<const uint32_t*>(&Bs[r * ROW_HALFS + k0 + lc * 2]);
                const uint32_t b1 = *reinterpret_cast<const uint32_t*>(&Bs[r * ROW_HALFS + k0 + lc * 2 + 8]);
                mma_f16(acc[0][ni], a[0], b0, b1);
                mma_f16(acc[1][ni], a[1], b0, b1);
            }
        }
    }

    // Epilogue: y = acc + bias  (C layout of m16n8k16 == m16n8k8)
    float* yb = y + (size_t)(bm * 128 + wm) * OUT_DIM + bn * 128 + wn;
    const float* biasb = bias + bn * 128 + wn;
#pragma unroll
    for (int mi = 0; mi < 2; mi++) {
#pragma unroll
        for (int ni = 0; ni < 8; ni++) {
            const int col = ni * 8 + lc * 2;
            const float2 bb = *reinterpret_cast<const float2*>(biasb + col);
            float2 v0 = make_float2(acc[mi][ni][0] + bb.x, acc[mi][ni][1] + bb.y);
            float2 v1 = make_float2(acc[mi][ni][2] + bb.x, acc[mi][ni][3] + bb.y);
            *reinterpret_cast<float2*>(yb + (size_t)(mi * 16 + lr) * OUT_DIM + col)     = v0;
            *reinterpret_cast<float2*>(yb + (size_t)(mi * 16 + lr + 8) * OUT_DIM + col) = v1;
        }
    }
}

// ---------------------------------------------------------------------------
extern "C" void kernel_launch(void* const* d_in, const int* in_sizes, int n_in,
                              void* d_out, int out_size)
{
    const float* x      = (const float*)d_in[0];
    const float* W      = (const float*)d_in[1];
    const float* bias   = (const float*)d_in[2];
    const float* w1a    = (const float*)d_in[3];
    const float* w1b    = (const float*)d_in[4];
    const float* w2a    = (const float*)d_in[5];
    const float* w2b    = (const float*)d_in[6];
    const float* scalar = (const float*)d_in[7];
    float* y = (float*)d_out;

    (void)in_sizes; (void)n_in; (void)out_size;

    static bool attr_set = false;
    if (!attr_set) {
        cudaFuncSetAttribute(gemm_f16_pipe,
                             cudaFuncAttributeMaxDynamicSharedMemorySize, SMEM_BYTES);
        attr_set = true;
    }

    prep_weight_kernel<<<dim3(IN_DIM / 256, OUT_DIM / 128), 256>>>(W, w1a, w1b, w2a, w2b, scalar);
    convert_x_kernel<<<(M_TOTAL * (size_t)IN_DIM / 4) / 256, 256>>>(x);
    gemm_f16_pipe<<<dim3(OUT_DIM / 128, M_TOTAL / 128), 256, SMEM_BYTES>>>(bias, y);
}

// round 9
// speedup vs baseline: 2.9537x; 1.2522x over previous
#include <cuda_runtime.h>
#include <cuda_fp16.h>
#include <cstdint>

// ---------------------------------------------------------------------------
// MockLoHAAdapter: y = x @ (W + (w1a@w1b)*(w2a@w2b)*scalar)^T + bias
// Round 8: fp16 m16n8k16 GEMM with ldmatrix fragment loads (4x fewer LDS)
// and 3-stage cp.async pipeline sized for 2 CTAs/SM.
// ---------------------------------------------------------------------------

#define IN_DIM   4096
#define OUT_DIM  4096
#define RANK     16
#define M_TOTAL  8192

#define BK        64                     // halfs per k-tile -> 128 B/row
#define NT        (IN_DIM / BK)          // 64 k-tiles
#define NSTAGE    3
#define ROW_HALFS 72                     // 64 + 8 pad (144 B, 16B-aligned)
#define TILE_HALFS (128 * ROW_HALFS)
#define STAGE_HALFS (2 * TILE_HALFS)     // A + B
#define SMEM_BYTES  (NSTAGE * STAGE_HALFS * 2)   // 110592 -> 2 CTAs/SM

// Device-global fp16 operands (allocation-free rule).
__device__ __half g_Wh[(size_t)OUT_DIM * IN_DIM];
__device__ __half g_Xh[(size_t)M_TOTAL * IN_DIM];

// ---------------------------------------------------------------------------
// Kernel 1: Wc = (W + (w1a@w1b)*(w2a@w2b)*scalar) -> fp16.
// ---------------------------------------------------------------------------
__global__ __launch_bounds__(256) void prep_weight_kernel(
    const float* __restrict__ W,
    const float* __restrict__ w1a, const float* __restrict__ w1b,
    const float* __restrict__ w2a, const float* __restrict__ w2b,
    const float* __restrict__ scalar)
{
    __shared__ float b1s[RANK][256];
    __shared__ float b2s[RANK][256];
    __shared__ float a1s[128][RANK];
    __shared__ float a2s[128][RANK];

    const int tid = threadIdx.x;
    const int i0 = blockIdx.x * 256;
    const int o0 = blockIdx.y * 128;
    const float s = scalar[0];

#pragma unroll
    for (int j = 0; j < RANK; j++) {
        b1s[j][tid] = w1b[j * IN_DIM + i0 + tid];
        b2s[j][tid] = w2b[j * IN_DIM + i0 + tid];
    }
#pragma unroll
    for (int j = 0; j < 8; j++) {
        const int idx = j * 256 + tid;
        a1s[idx >> 4][idx & 15] = w1a[(o0 + (idx >> 4)) * RANK + (idx & 15)];
        a2s[idx >> 4][idx & 15] = w2a[(o0 + (idx >> 4)) * RANK + (idx & 15)];
    }
    __syncthreads();

    float b1v[RANK], b2v[RANK];
#pragma unroll
    for (int r = 0; r < RANK; r++) { b1v[r] = b1s[r][tid]; b2v[r] = b2s[r][tid]; }

    for (int o = 0; o < 128; o++) {
        float s1 = 0.f, s2 = 0.f;
#pragma unroll
        for (int r = 0; r < RANK; r++) {
            s1 = fmaf(a1s[o][r], b1v[r], s1);
            s2 = fmaf(a2s[o][r], b2v[r], s2);
        }
        const float w = __ldg(&W[(size_t)(o0 + o) * IN_DIM + i0 + tid]);
        g_Wh[(size_t)(o0 + o) * IN_DIM + i0 + tid] = __float2half_rn(w + s1 * s2 * s);
    }
}

// ---------------------------------------------------------------------------
// Kernel 2: x -> fp16.
// ---------------------------------------------------------------------------
__global__ __launch_bounds__(256) void convert_x_kernel(const float* __restrict__ x)
{
    const size_t i = (size_t)blockIdx.x * blockDim.x + threadIdx.x;
    const float4 v = __ldg(reinterpret_cast<const float4*>(x) + i);
    const __half2 h0 = __floats2half2_rn(v.x, v.y);
    const __half2 h1 = __floats2half2_rn(v.z, v.w);
    uint2 o;
    o.x = *reinterpret_cast<const uint32_t*>(&h0);
    o.y = *reinterpret_cast<const uint32_t*>(&h1);
    reinterpret_cast<uint2*>(g_Xh)[i] = o;
}

// ---------------------------------------------------------------------------
// Kernel 3: fp16 GEMM. BM=BN=128, BK=64, 256 thr (8 warps: 4M x 2N).
// ldmatrix fragment loads, 3-stage cp.async, 2 CTAs/SM.
// ---------------------------------------------------------------------------
__device__ __forceinline__ void mma_f16(float c[4], const uint32_t a[4],
                                        uint32_t b0, uint32_t b1) {
    asm volatile(
        "mma.sync.aligned.m16n8k16.row.col.f32.f16.f16.f32 "
        "{%0,%1,%2,%3}, {%4,%5,%6,%7}, {%8,%9}, {%0,%1,%2,%3};"
        : "+f"(c[0]), "+f"(c[1]), "+f"(c[2]), "+f"(c[3])
        : "r"(a[0]), "r"(a[1]), "r"(a[2]), "r"(a[3]), "r"(b0), "r"(b1));
}

__device__ __forceinline__ void ldmatrix_x4(uint32_t& r0, uint32_t& r1,
                                            uint32_t& r2, uint32_t& r3,
                                            uint32_t saddr) {
    asm volatile("ldmatrix.sync.aligned.m8n8.x4.shared.b16 {%0,%1,%2,%3}, [%4];"
                 : "=r"(r0), "=r"(r1), "=r"(r2), "=r"(r3) : "r"(saddr));
}

__device__ __forceinline__ void cp_async16(uint32_t smem_addr, const void* gptr) {
    asm volatile("cp.async.cg.shared.global [%0], [%1], 16;\n"
                 :: "r"(smem_addr), "l"(gptr));
}

__global__ __launch_bounds__(256, 2) void gemm_f16_pipe(
    const float* __restrict__ bias, float* __restrict__ y)
{
    extern __shared__ __align__(16) __half sm[];

    const int tid  = threadIdx.x;
    const int lane = tid & 31;
    const int warp = tid >> 5;
    const int wm   = (warp >> 1) * 32;   // warp M offset (4 warps in M)
    const int wn   = (warp & 1) * 64;    // warp N offset (2 warps in N)
    const int lr   = lane >> 2;          // 0..7
    const int lc   = lane & 3;           // 0..3

    const int bm = blockIdx.y;
    const int bn = blockIdx.x;

    const __half* Aptr = g_Xh + (size_t)(bm * 128) * IN_DIM;
    const __half* Bptr = g_Wh + (size_t)(bn * 128) * IN_DIM;

    const uint32_t smem_base = (uint32_t)__cvta_generic_to_shared(sm);

    auto issue_stage = [&](int kt, int s) {
        const uint32_t st = smem_base + (uint32_t)(s * STAGE_HALFS) * 2;
        const int kofs = kt * BK;
#pragma unroll
        for (int p = 0; p < 4; p++) {
            const int c = p * 256 + tid;
            const int row = c >> 3;
            const int col16 = c & 7;
            const uint32_t so = (uint32_t)(row * ROW_HALFS * 2 + col16 * 16);
            const size_t go = (size_t)row * IN_DIM + kofs + col16 * 8;
            cp_async16(st + so,                  Aptr + go);
            cp_async16(st + TILE_HALFS * 2 + so, Bptr + go);
        }
    };

    // ldmatrix per-lane row/col selectors (same for every ks; col k0 added later).
    // A (m16k16): sub0 rows0-7@k0, sub1 rows8-15@k0, sub2 rows0-7@k8, sub3 rows8-15@k8
    const int a_row = (lane & 7) + ((lane & 8) ? 8 : 0);
    const int a_col = (lane & 16) ? 8 : 0;
    // B (n16k16 pair): sub0 n0-7@k0 (b0 lo), sub1 n0-7@k8 (b1 lo),
    //                  sub2 n8-15@k0 (b0 hi), sub3 n8-15@k8 (b1 hi)
    const int b_row = (lane & 7) + ((lane & 16) ? 8 : 0);
    const int b_col = (lane & 8) ? 8 : 0;

    float acc[2][8][4];
#pragma unroll
    for (int mi = 0; mi < 2; mi++)
#pragma unroll
        for (int ni = 0; ni < 8; ni++)
#pragma unroll
            for (int q = 0; q < 4; q++) acc[mi][ni][q] = 0.f;

#pragma unroll
    for (int i = 0; i < NSTAGE - 1; i++) {
        issue_stage(i, i);
        asm volatile("cp.async.commit_group;\n" ::);
    }

    for (int kt = 0; kt < NT; kt++) {
        asm volatile("cp.async.wait_group %0;\n" :: "n"(NSTAGE - 2));
        __syncthreads();

        if (kt + NSTAGE - 1 < NT) issue_stage(kt + NSTAGE - 1, (kt + NSTAGE - 1) % NSTAGE);
        asm volatile("cp.async.commit_group;\n" ::);

        const int s = kt % NSTAGE;
        const uint32_t As = smem_base + (uint32_t)(s * STAGE_HALFS) * 2;
        const uint32_t Bs = As + TILE_HALFS * 2;

#pragma unroll
        for (int ks = 0; ks < 4; ks++) {
            const int k0 = ks * 16;
            // A fragments: 2 ldmatrix.x4 (one per 16-row group)
            uint32_t a[2][4];
#pragma unroll
            for (int mi = 0; mi < 2; mi++) {
                const uint32_t addr = As +
                    (uint32_t)((wm + mi * 16 + a_row) * ROW_HALFS + k0 + a_col) * 2;
                ldmatrix_x4(a[mi][0], a[mi][1], a[mi][2], a[mi][3], addr);
            }
            // B fragments: 4 ldmatrix.x4, each covering a 16-n pair
            uint32_t b[8][2];
#pragma unroll
            for (int np = 0; np < 4; np++) {
                const uint32_t addr = Bs +
                    (uint32_t)((wn + np * 16 + b_row) * ROW_HALFS + k0 + b_col) * 2;
                ldmatrix_x4(b[np * 2][0], b[np * 2][1], b[np * 2 + 1][0], b[np * 2 + 1][1], addr);
            }
#pragma unroll
            for (int ni = 0; ni < 8; ni++) {
                mma_f16(acc[0][ni], a[0], b[ni][0], b[ni][1]);
                mma_f16(acc[1][ni], a[1], b[ni][0], b[ni][1]);
            }
        }
    }

    // Epilogue: y = acc + bias
    float* yb = y + (size_t)(bm * 128 + wm) * OUT_DIM + bn * 128 + wn;
    const float* biasb = bias + bn * 128 + wn;
#pragma unroll
    for (int mi = 0; mi < 2; mi++) {
#pragma unroll
        for (int ni = 0; ni < 8; ni++) {
            const int col = ni * 8 + lc * 2;
            const float2 bb = *reinterpret_cast<const float2*>(biasb + col);
            float2 v0 = make_float2(acc[mi][ni][0] + bb.x, acc[mi][ni][1] + bb.y);
            float2 v1 = make_float2(acc[mi][ni][2] + bb.x, acc[mi][ni][3] + bb.y);
            *reinterpret_cast<float2*>(yb + (size_t)(mi * 16 + lr) * OUT_DIM + col)     = v0;
            *reinterpret_cast<float2*>(yb + (size_t)(mi * 16 + lr + 8) * OUT_DIM + col) = v1;
        }
    }
}

// ---------------------------------------------------------------------------
extern "C" void kernel_launch(void* const* d_in, const int* in_sizes, int n_in,
                              void* d_out, int out_size)
{
    const float* x      = (const float*)d_in[0];
    const float* W      = (const float*)d_in[1];
    const float* bias   = (const float*)d_in[2];
    const float* w1a    = (const float*)d_in[3];
    const float* w1b    = (const float*)d_in[4];
    const float* w2a    = (const float*)d_in[5];
    const float* w2b    = (const float*)d_in[6];
    const float* scalar = (const float*)d_in[7];
    float* y = (float*)d_out;

    (void)in_sizes; (void)n_in; (void)out_size;

    static bool attr_set = false;
    if (!attr_set) {
        cudaFuncSetAttribute(gemm_f16_pipe,
                             cudaFuncAttributeMaxDynamicSharedMemorySize, SMEM_BYTES);
        attr_set = true;
    }

    prep_weight_kernel<<<dim3(IN_DIM / 256, OUT_DIM / 128), 256>>>(W, w1a, w1b, w2a, w2b, scalar);
    convert_x_kernel<<<(M_TOTAL * (size_t)IN_DIM / 4) / 256, 256>>>(x);
    gemm_f16_pipe<<<dim3(OUT_DIM / 128, M_TOTAL / 128), 256, SMEM_BYTES>>>(bias, y);
}